// round 1
// baseline (speedup 1.0000x reference)
#include <cuda_runtime.h>

// 9x9 zero-padded box filter over 128 independent 512x512 fp32 images.
// Separable: horizontal 9-sum (register-sliding over float4 smem loads),
// then vertical 9-sum (register-sliding over float4 smem loads), float4
// coalesced global writes.

#define RR 4
#define W  512
#define H  512
#define TW 128                 // output tile width
#define TH 32                  // output tile height
#define SW (TW + 2*RR)         // 136 (x 4B = 544B, 16B aligned rows)
#define SH (TH + 2*RR)         // 40
#define NT 256

__global__ __launch_bounds__(NT) void box9_kernel(const float* __restrict__ x,
                                                  float* __restrict__ out) {
    __shared__ __align__(16) float s_in[SH][SW];   // 21760 B
    __shared__ __align__(16) float s_h [SH][TW];   // 20480 B

    const int img = blockIdx.z;
    const int x0  = blockIdx.x * TW;
    const int y0  = blockIdx.y * TH;
    const float* __restrict__ base  = x   + (size_t)img * (W * H);
    float* __restrict__       obase = out + (size_t)img * (W * H);
    const int t = threadIdx.x;

    // ---- load input tile + halo (zero padding outside the image) ----
    for (int idx = t; idx < SH * SW; idx += NT) {
        int r = idx / SW;
        int c = idx - r * SW;
        int gy = y0 + r - RR;
        int gx = x0 + c - RR;
        float v = 0.0f;
        if ((unsigned)gy < (unsigned)H && (unsigned)gx < (unsigned)W)
            v = __ldg(&base[gy * W + gx]);
        s_in[r][c] = v;
    }
    __syncthreads();

    // ---- horizontal pass: h[r][c] = sum_{d=0..8} s_in[r][c+d] ----
    // Each group of 4 output columns needs 3 aligned float4 loads.
    const float4* sin4 = reinterpret_cast<const float4*>(&s_in[0][0]); // row stride SW/4 = 34
    float4*       h4   = reinterpret_cast<float4*>(&s_h[0][0]);        // row stride TW/4 = 32
    for (int g = t; g < SH * (TW / 4); g += NT) {
        int r  = g >> 5;        // g / 32
        int gc = g & 31;        // col group (4 cols)
        float4 a = sin4[r * (SW / 4) + gc];
        float4 b = sin4[r * (SW / 4) + gc + 1];
        float4 c = sin4[r * (SW / 4) + gc + 2];
        float s8 = ((a.x + a.y) + (a.z + a.w)) + ((b.x + b.y) + (b.z + b.w));
        float h0 = s8 + c.x;            // cols c..c+8
        float h1 = h0 - a.x + c.y;      // slide
        float h2 = h1 - a.y + c.z;
        float h3 = h2 - a.z + c.w;
        h4[r * (TW / 4) + gc] = make_float4(h0, h1, h2, h3);
    }
    __syncthreads();

    // ---- vertical pass: out[ro][c] = sum_{d=0..8} h[ro+d][c] ----
    // 256 threads = 8 row-segments x 32 col-groups. Each thread produces a
    // 4x4 output patch from 12 float4 rows via a vertical sliding window.
    for (int g = t; g < (TH / 4) * (TW / 4); g += NT) {
        int rs = g >> 5;        // row segment 0..7
        int gc = g & 31;        // col group
        int r0 = rs * 4;
        float4 h[12];
        #pragma unroll
        for (int i = 0; i < 12; i++)
            h[i] = h4[(r0 + i) * (TW / 4) + gc];

        float4 s = h[0];
        #pragma unroll
        for (int i = 1; i < 9; i++) {
            s.x += h[i].x; s.y += h[i].y; s.z += h[i].z; s.w += h[i].w;
        }
        #pragma unroll
        for (int i = 0; i < 4; i++) {
            float4* orow = reinterpret_cast<float4*>(obase + (size_t)(y0 + r0 + i) * W + x0);
            orow[gc] = s;       // coalesced 16B stores, warp = 512B row segment
            if (i < 3) {
                s.x = s.x - h[i].x + h[i + 9].x;
                s.y = s.y - h[i].y + h[i + 9].y;
                s.z = s.z - h[i].z + h[i + 9].z;
                s.w = s.w - h[i].w + h[i + 9].w;
            }
        }
    }
}

extern "C" void kernel_launch(void* const* d_in, const int* in_sizes, int n_in,
                              void* d_out, int out_size) {
    const float* x = (const float*)d_in[0];
    float* out = (float*)d_out;
    int nimg = in_sizes[0] / (W * H);        // 8*16 = 128
    dim3 grid(W / TW, H / TH, nimg);         // (4, 16, 128)
    box9_kernel<<<grid, NT>>>(x, out);
}

// round 3
// speedup vs baseline: 1.6186x; 1.6186x over previous
#include <cuda_runtime.h>

// 9x9 zero-padded box filter, 128 independent 512x512 fp32 images.
// Full-width row pipeline: each CTA = one 512-wide x TH-row band of one image.
// Vertical 9-sum slides in registers (new row from DRAM, old row from L1/L2),
// horizontal 9-sum via one smem float4 store + 2 neighbor float4 loads.

#define W   512
#define H   512
#define TH  64                  // rows per CTA band
#define NT  128                 // one thread per float4 column group (512/4)
#define W4  (W / 4)             // 128

__global__ __launch_bounds__(NT) void box9_kernel(const float* __restrict__ xin,
                                                  float* __restrict__ outp) {
    // 4 row-buffers (2 rows in flight per barrier, alternating pairs).
    // Slot s holds cols 4(s-1)..4(s-1)+3; slots 0 and 129 are the zero halo.
    __shared__ __align__(16) float4 buf[4][132];

    const int t  = threadIdx.x;
    const int y0 = blockIdx.x * TH;
    const size_t imgoff = (size_t)blockIdx.y * (W * H);
    const float4* __restrict__ base  = reinterpret_cast<const float4*>(xin + imgoff);
    float4* __restrict__       obase = reinterpret_cast<float4*>(outp + imgoff);

    if (t < 4) {
        buf[t][0]   = make_float4(0.f, 0.f, 0.f, 0.f);
        buf[t][129] = make_float4(0.f, 0.f, 0.f, 0.f);
    }

    // ---- prologue: vs = sum of input rows [y0-5, y0+3] (zeros outside) ----
    // Invariant before the update at output row y: vs = sum rows [y-5, y+3].
    float4 vs = make_float4(0.f, 0.f, 0.f, 0.f);
    #pragma unroll
    for (int i = -5; i <= 3; i++) {
        int r = y0 + i;
        if ((unsigned)r < (unsigned)H) {
            float4 v = base[r * W4 + t];
            vs.x += v.x; vs.y += v.y; vs.z += v.z; vs.w += v.w;
        }
    }

    // prefetch rows for the first iteration (output rows y0, y0+1):
    //   n = x[y+4], o = x[y-5]
    float4 n0 = make_float4(0.f,0.f,0.f,0.f), o0 = n0, n1 = n0, o1 = n0;
    { int r;
      r = y0 + 4; if ((unsigned)r < (unsigned)H) n0 = base[r * W4 + t];
      r = y0 - 5; if ((unsigned)r < (unsigned)H) o0 = base[r * W4 + t];
      r = y0 + 5; if ((unsigned)r < (unsigned)H) n1 = base[r * W4 + t];
      r = y0 - 4; if ((unsigned)r < (unsigned)H) o1 = base[r * W4 + t];
    }

    #pragma unroll 2
    for (int k = 0; k < TH / 2; k++) {
        const int y = y0 + 2 * k;
        float4 na = n0, oa = o0, nb = n1, ob = o1;

        // prefetch rows for next iteration (output rows y+2, y+3)
        if (k + 1 < TH / 2) {
            int r;
            n0 = make_float4(0.f,0.f,0.f,0.f); o0 = n0; n1 = n0; o1 = n0;
            r = y + 6; if ((unsigned)r < (unsigned)H) n0 = base[r * W4 + t];
            r = y - 3; if ((unsigned)r < (unsigned)H) o0 = base[r * W4 + t];
            r = y + 7; if ((unsigned)r < (unsigned)H) n1 = base[r * W4 + t];
            r = y - 2; if ((unsigned)r < (unsigned)H) o1 = base[r * W4 + t];
        }

        // vertical slide, two rows
        vs.x += na.x - oa.x; vs.y += na.y - oa.y;
        vs.z += na.z - oa.z; vs.w += na.w - oa.w;
        float4 vs0 = vs;
        buf[(2 * k) & 3][t + 1] = vs0;

        vs.x += nb.x - ob.x; vs.y += nb.y - ob.y;
        vs.z += nb.z - ob.z; vs.w += nb.w - ob.w;
        float4 vs1 = vs;
        buf[(2 * k + 1) & 3][t + 1] = vs1;

        __syncthreads();

        // horizontal slide, row y
        {
            float4 a = buf[(2 * k) & 3][t];
            float4 c = buf[(2 * k) & 3][t + 2];
            float sb = (vs0.x + vs0.y) + (vs0.z + vs0.w);
            float sa = (a.x + a.y) + (a.z + a.w);
            float h0 = sa + sb + c.x;
            float h1 = h0 - a.x + c.y;
            float h2 = h1 - a.y + c.z;
            float h3 = h2 - a.z + c.w;
            obase[y * W4 + t] = make_float4(h0, h1, h2, h3);
        }
        // horizontal slide, row y+1
        {
            float4 a = buf[(2 * k + 1) & 3][t];
            float4 c = buf[(2 * k + 1) & 3][t + 2];
            float sb = (vs1.x + vs1.y) + (vs1.z + vs1.w);
            float sa = (a.x + a.y) + (a.z + a.w);
            float h0 = sa + sb + c.x;
            float h1 = h0 - a.x + c.y;
            float h2 = h1 - a.y + c.z;
            float h3 = h2 - a.z + c.w;
            obase[(y + 1) * W4 + t] = make_float4(h0, h1, h2, h3);
        }
    }
}

extern "C" void kernel_launch(void* const* d_in, const int* in_sizes, int n_in,
                              void* d_out, int out_size) {
    const float* x = (const float*)d_in[0];
    float* out = (float*)d_out;
    int nimg = in_sizes[0] / (W * H);     // 128
    dim3 grid(H / TH, nimg);              // (8, 128) = 1024 CTAs
    box9_kernel<<<grid, NT>>>(x, out);
}